// round 9
// baseline (speedup 1.0000x reference)
#include <cuda_runtime.h>
#include <cuda_bf16.h>
#include <cstdint>

// ---------------------------------------------------------------------------
// CompressedMoEBlock: sparse top-2 MoE with factored experts (fp32 baseline)
//   T=2048 tokens, E=8 experts, K=2, H=1024, R=256, F=2816
// Pipeline (per launch, all on default stream, graph-capturable):
//   init -> gate(top2 + counts) -> prefix(padded offsets) -> assign(gather lists)
//   -> 9 per-expert batched GEMMs (128x128x8 fp32 tiles) -> combine
// ---------------------------------------------------------------------------

namespace {
constexpr int T    = 2048;
constexpr int Hd   = 1024;
constexpr int E    = 8;
constexpr int R    = 256;
constexpr int F    = 2816;
constexpr int BM   = 128;
constexpr int MCAP = 5120;   // sum of per-expert 128-padded counts <= 4096 + 8*127
}

// ------------------------- device scratch (no allocs) -----------------------
__device__ int   d_cnt[E];
__device__ int   d_cnt2[E];
__device__ int   d_poff[E];
__device__ int   d_pcnt[E];
__device__ int   d_toklist[MCAP];
__device__ int   d_tkidx[T * 2];
__device__ int   d_slotmap[T * 2];
__device__ float d_wrow[MCAP];
__device__ float d_tkw[T * 2];

__device__ float d_Pg [MCAP * R];
__device__ float d_Pg2[MCAP * R];
__device__ float d_Pu [MCAP * R];
__device__ float d_Pu2[MCAP * R];
__device__ float d_Qd [MCAP * R];
__device__ float d_Qd2[MCAP * R];
__device__ float d_Abuf[(size_t)MCAP * F];   // ~57.7 MB
__device__ float d_Y  [MCAP * Hd];           // ~21 MB

__device__ __forceinline__ float silu_f(float v) {
    return v / (1.0f + __expf(-v));
}

// ------------------------- setup kernels -----------------------------------
__global__ void init_kernel() {
    int i = threadIdx.x;
    if (i < E) { d_cnt[i] = 0; d_cnt2[i] = 0; }
    for (int j = i; j < MCAP; j += 256) { d_toklist[j] = 0; d_wrow[j] = 0.0f; }
}

__global__ void __launch_bounds__(256) gate_kernel(const float* __restrict__ x,
                                                   const float* __restrict__ gw) {
    __shared__ float sgw[Hd * E];   // 32 KB
    const int t = blockIdx.x * 256 + threadIdx.x;
    for (int i = threadIdx.x; i < Hd * E; i += 256) sgw[i] = gw[i];
    __syncthreads();

    float lg[E];
    #pragma unroll
    for (int e = 0; e < E; e++) lg[e] = 0.0f;

    const float4* x4 = (const float4*)(x + (long)t * Hd);
    for (int h4 = 0; h4 < Hd / 4; h4++) {
        float4 xv = x4[h4];
        const float* g = &sgw[(h4 * 4) * E];
        #pragma unroll
        for (int e = 0; e < E; e++) lg[e] += xv.x * g[e];
        #pragma unroll
        for (int e = 0; e < E; e++) lg[e] += xv.y * g[E + e];
        #pragma unroll
        for (int e = 0; e < E; e++) lg[e] += xv.z * g[2 * E + e];
        #pragma unroll
        for (int e = 0; e < E; e++) lg[e] += xv.w * g[3 * E + e];
    }

    float mx = lg[0];
    #pragma unroll
    for (int e = 1; e < E; e++) mx = fmaxf(mx, lg[e]);
    float p[E], s = 0.0f;
    #pragma unroll
    for (int e = 0; e < E; e++) { p[e] = __expf(lg[e] - mx); s += p[e]; }
    float inv = 1.0f / s;
    #pragma unroll
    for (int e = 0; e < E; e++) p[e] *= inv;

    // top-2, strict '>' ascending scan matches jax top_k tie-breaking
    int e0 = 0;
    #pragma unroll
    for (int e = 1; e < E; e++) if (p[e] > p[e0]) e0 = e;
    int e1 = (e0 == 0) ? 1 : 0;
    #pragma unroll
    for (int e = 0; e < E; e++) if (e != e0 && p[e] > p[e1]) e1 = e;

    float w0 = p[e0], w1 = p[e1];
    float ws = 1.0f / (w0 + w1);
    w0 *= ws; w1 *= ws;

    d_tkidx[t * 2 + 0] = e0;  d_tkidx[t * 2 + 1] = e1;
    d_tkw  [t * 2 + 0] = w0;  d_tkw  [t * 2 + 1] = w1;
    atomicAdd(&d_cnt[e0], 1);
    atomicAdd(&d_cnt[e1], 1);
}

__global__ void prefix_kernel() {
    int acc = 0;
    for (int e = 0; e < E; e++) {
        int pc = (d_cnt[e] + (BM - 1)) & ~(BM - 1);
        d_poff[e] = acc;
        d_pcnt[e] = pc;
        acc += pc;
    }
}

__global__ void assign_kernel() {
    int t = blockIdx.x * 256 + threadIdx.x;
    #pragma unroll
    for (int k = 0; k < 2; k++) {
        int e = d_tkidx[t * 2 + k];
        int s = atomicAdd(&d_cnt2[e], 1);
        int g = d_poff[e] + s;
        d_toklist[g]        = t;
        d_wrow[g]           = d_tkw[t * 2 + k];
        d_slotmap[t * 2 + k] = g;
    }
}

// ------------------------- generic tile GEMM --------------------------------
// C[rows of expert e] = A @ (B + e*sBe)   128x128x8 tiles, 256 thr, 8x8/thread
// GATHER: A row index via d_toklist (rows of global input x)
// EPI: 0 = store; 1 = C = silu(C_prev) * acc (in-place act-fuse); 2 = C = wrow * acc
template<bool GATHER, int EPI>
__device__ __forceinline__ void gemm_body(
    const float* __restrict__ A, const float* __restrict__ B,
    float* __restrict__ C, int K, int N, long sBe,
    const float* __restrict__ wr)
{
    const int e       = blockIdx.z;
    const int m0      = d_poff[e];
    const int M       = d_pcnt[e];
    const int rowTile = blockIdx.y * BM;
    if (rowTile >= M) return;

    __shared__ float As[8][BM];
    __shared__ float Bs[8][128];

    const int tid  = threadIdx.x;
    const int aRow = tid >> 1;
    const int aCol = (tid & 1) * 4;
    const int bRow = tid >> 5;
    const int bCol = (tid & 31) * 4;

    long arow;
    if (GATHER) arow = d_toklist[m0 + rowTile + aRow];
    else        arow = (long)(m0 + rowTile + aRow);
    const float* Ap = A + arow * K + aCol;
    const float* Bp = B + (long)e * sBe + (long)blockIdx.x * 128
                        + (long)bRow * N + bCol;

    const int tx = tid & 15;
    const int ty = tid >> 4;

    float acc[8][8];
    #pragma unroll
    for (int i = 0; i < 8; i++)
        #pragma unroll
        for (int j = 0; j < 8; j++) acc[i][j] = 0.0f;

    for (int kt = 0; kt < K; kt += 8) {
        float4 av = *(const float4*)(Ap + kt);
        As[aCol + 0][aRow] = av.x;
        As[aCol + 1][aRow] = av.y;
        As[aCol + 2][aRow] = av.z;
        As[aCol + 3][aRow] = av.w;
        *(float4*)(&Bs[bRow][bCol]) = *(const float4*)(Bp + (long)kt * N);
        __syncthreads();

        #pragma unroll
        for (int kk = 0; kk < 8; kk++) {
            float4 a0 = *(const float4*)(&As[kk][ty * 8]);
            float4 a1 = *(const float4*)(&As[kk][ty * 8 + 4]);
            float4 b0 = *(const float4*)(&Bs[kk][tx * 8]);
            float4 b1 = *(const float4*)(&Bs[kk][tx * 8 + 4]);
            float ra[8] = {a0.x, a0.y, a0.z, a0.w, a1.x, a1.y, a1.z, a1.w};
            float rb[8] = {b0.x, b0.y, b0.z, b0.w, b1.x, b1.y, b1.z, b1.w};
            #pragma unroll
            for (int i = 0; i < 8; i++)
                #pragma unroll
                for (int j = 0; j < 8; j++) acc[i][j] += ra[i] * rb[j];
        }
        __syncthreads();
    }

    const int crow0 = m0 + rowTile + ty * 8;
    const int ccol0 = blockIdx.x * 128 + tx * 8;
    #pragma unroll
    for (int i = 0; i < 8; i++) {
        float* cp = C + (long)(crow0 + i) * N + ccol0;
        if (EPI == 0) {
            float4 v0 = {acc[i][0], acc[i][1], acc[i][2], acc[i][3]};
            float4 v1 = {acc[i][4], acc[i][5], acc[i][6], acc[i][7]};
            *(float4*)cp       = v0;
            *(float4*)(cp + 4) = v1;
        } else if (EPI == 1) {
            float4 g0 = *(const float4*)cp;
            float4 g1 = *(const float4*)(cp + 4);
            float4 v0 = {silu_f(g0.x) * acc[i][0], silu_f(g0.y) * acc[i][1],
                         silu_f(g0.z) * acc[i][2], silu_f(g0.w) * acc[i][3]};
            float4 v1 = {silu_f(g1.x) * acc[i][4], silu_f(g1.y) * acc[i][5],
                         silu_f(g1.z) * acc[i][6], silu_f(g1.w) * acc[i][7]};
            *(float4*)cp       = v0;
            *(float4*)(cp + 4) = v1;
        } else {
            float w = wr[crow0 + i];
            float4 v0 = {w * acc[i][0], w * acc[i][1], w * acc[i][2], w * acc[i][3]};
            float4 v1 = {w * acc[i][4], w * acc[i][5], w * acc[i][6], w * acc[i][7]};
            *(float4*)cp       = v0;
            *(float4*)(cp + 4) = v1;
        }
    }
}

// Thin wrappers binding the __device__ scratch (avoids host symbol lookups)
__global__ void __launch_bounds__(256) k_pg(const float* x, const float* Ug) {
    gemm_body<true, 0>(x, Ug, d_Pg, Hd, R, (long)Hd * R, nullptr);
}
__global__ void __launch_bounds__(256) k_pu(const float* x, const float* Uu) {
    gemm_body<true, 0>(x, Uu, d_Pu, Hd, R, (long)Hd * R, nullptr);
}
__global__ void __launch_bounds__(256) k_pg2(const float* Cg) {
    gemm_body<false, 0>(d_Pg, Cg, d_Pg2, R, R, 0, nullptr);
}
__global__ void __launch_bounds__(256) k_pu2(const float* Cu) {
    gemm_body<false, 0>(d_Pu, Cu, d_Pu2, R, R, 0, nullptr);
}
__global__ void __launch_bounds__(256) k_g(const float* Vg) {
    gemm_body<false, 0>(d_Pg2, Vg, d_Abuf, R, F, (long)R * F, nullptr);
}
__global__ void __launch_bounds__(256) k_act(const float* Vu) {
    gemm_body<false, 1>(d_Pu2, Vu, d_Abuf, R, F, (long)R * F, nullptr);
}
__global__ void __launch_bounds__(256) k_qd(const float* Ud) {
    gemm_body<false, 0>(d_Abuf, Ud, d_Qd, F, R, (long)F * R, nullptr);
}
__global__ void __launch_bounds__(256) k_qd2(const float* Cd) {
    gemm_body<false, 0>(d_Qd, Cd, d_Qd2, R, R, 0, nullptr);
}
__global__ void __launch_bounds__(256) k_y(const float* Vd) {
    gemm_body<false, 2>(d_Qd2, Vd, d_Y, R, Hd, (long)R * Hd, d_wrow);
}

// Final combine: out[t] = Y[slot0(t)] + Y[slot1(t)]  (weights folded into Y)
__global__ void __launch_bounds__(256) combine_kernel(float* __restrict__ out) {
    int i = blockIdx.x * 256 + threadIdx.x;   // over T*Hd/4 float4s
    int t = i >> 8;                           // Hd/4 = 256
    int c = i & 255;
    int s0 = d_slotmap[t * 2 + 0];
    int s1 = d_slotmap[t * 2 + 1];
    const float4* Y4 = (const float4*)d_Y;
    float4 a = Y4[(long)s0 * 256 + c];
    float4 b = Y4[(long)s1 * 256 + c];
    float4 o = {a.x + b.x, a.y + b.y, a.z + b.z, a.w + b.w};
    ((float4*)out)[i] = o;
}

// ------------------------- launch -------------------------------------------
extern "C" void kernel_launch(void* const* d_in, const int* in_sizes, int n_in,
                              void* d_out, int out_size) {
    const float* x  = (const float*)d_in[0];
    const float* gw = (const float*)d_in[1];
    const float* Ug = (const float*)d_in[2];
    const float* Cg = (const float*)d_in[3];
    const float* Vg = (const float*)d_in[4];
    const float* Uu = (const float*)d_in[5];
    const float* Cu = (const float*)d_in[6];
    const float* Vu = (const float*)d_in[7];
    const float* Ud = (const float*)d_in[8];
    const float* Cd = (const float*)d_in[9];
    const float* Vd = (const float*)d_in[10];
    float* out = (float*)d_out;

    init_kernel  <<<1, 256>>>();
    gate_kernel  <<<T / 256, 256>>>(x, gw);
    prefix_kernel<<<1, 1>>>();
    assign_kernel<<<T / 256, 256>>>();

    const dim3 blk(256, 1, 1);
    k_pg  <<<dim3(R  / 128, 16, E), blk>>>(x, Ug);
    k_pu  <<<dim3(R  / 128, 16, E), blk>>>(x, Uu);
    k_pg2 <<<dim3(R  / 128, 16, E), blk>>>(Cg);
    k_pu2 <<<dim3(R  / 128, 16, E), blk>>>(Cu);
    k_g   <<<dim3(F  / 128, 16, E), blk>>>(Vg);
    k_act <<<dim3(F  / 128, 16, E), blk>>>(Vu);
    k_qd  <<<dim3(R  / 128, 16, E), blk>>>(Ud);
    k_qd2 <<<dim3(R  / 128, 16, E), blk>>>(Cd);
    k_y   <<<dim3(Hd / 128, 16, E), blk>>>(Vd);

    combine_kernel<<<(T * Hd / 4) / 256, 256>>>(out);
}

// round 10
// speedup vs baseline: 1.0066x; 1.0066x over previous
#include <cuda_runtime.h>
#include <cuda_bf16.h>
#include <cstdint>

// ---------------------------------------------------------------------------
// CompressedMoEBlock: sparse top-2 MoE with factored experts (fp32 baseline)
//   T=2048 tokens, E=8 experts, K=2, H=1024, R=256, F=2816
// Pipeline (per launch, all on default stream, graph-capturable):
//   init -> gate(top2 + counts) -> prefix(padded offsets) -> assign(gather lists)
//   -> 9 per-expert batched GEMMs (128x128x8 fp32 tiles) -> combine
// ---------------------------------------------------------------------------

namespace {
constexpr int T    = 2048;
constexpr int Hd   = 1024;
constexpr int E    = 8;
constexpr int R    = 256;
constexpr int F    = 2816;
constexpr int BM   = 128;
constexpr int MCAP = 5120;   // sum of per-expert 128-padded counts <= 4096 + 8*127
}

// ------------------------- device scratch (no allocs) -----------------------
__device__ int   d_cnt[E];
__device__ int   d_cnt2[E];
__device__ int   d_poff[E];
__device__ int   d_pcnt[E];
__device__ int   d_toklist[MCAP];
__device__ int   d_tkidx[T * 2];
__device__ int   d_slotmap[T * 2];
__device__ float d_wrow[MCAP];
__device__ float d_tkw[T * 2];

__device__ float d_Pg [MCAP * R];
__device__ float d_Pg2[MCAP * R];
__device__ float d_Pu [MCAP * R];
__device__ float d_Pu2[MCAP * R];
__device__ float d_Qd [MCAP * R];
__device__ float d_Qd2[MCAP * R];
__device__ float d_Abuf[(size_t)MCAP * F];   // ~57.7 MB
__device__ float d_Y  [MCAP * Hd];           // ~21 MB

__device__ __forceinline__ float silu_f(float v) {
    return v / (1.0f + __expf(-v));
}

// ------------------------- setup kernels -----------------------------------
__global__ void init_kernel() {
    int i = threadIdx.x;
    if (i < E) { d_cnt[i] = 0; d_cnt2[i] = 0; }
    for (int j = i; j < MCAP; j += 256) { d_toklist[j] = 0; d_wrow[j] = 0.0f; }
}

__global__ void __launch_bounds__(256) gate_kernel(const float* __restrict__ x,
                                                   const float* __restrict__ gw) {
    __shared__ float sgw[Hd * E];   // 32 KB
    const int t = blockIdx.x * 256 + threadIdx.x;
    for (int i = threadIdx.x; i < Hd * E; i += 256) sgw[i] = gw[i];
    __syncthreads();

    float lg[E];
    #pragma unroll
    for (int e = 0; e < E; e++) lg[e] = 0.0f;

    const float4* x4 = (const float4*)(x + (long)t * Hd);
    for (int h4 = 0; h4 < Hd / 4; h4++) {
        float4 xv = x4[h4];
        const float* g = &sgw[(h4 * 4) * E];
        #pragma unroll
        for (int e = 0; e < E; e++) lg[e] += xv.x * g[e];
        #pragma unroll
        for (int e = 0; e < E; e++) lg[e] += xv.y * g[E + e];
        #pragma unroll
        for (int e = 0; e < E; e++) lg[e] += xv.z * g[2 * E + e];
        #pragma unroll
        for (int e = 0; e < E; e++) lg[e] += xv.w * g[3 * E + e];
    }

    float mx = lg[0];
    #pragma unroll
    for (int e = 1; e < E; e++) mx = fmaxf(mx, lg[e]);
    float p[E], s = 0.0f;
    #pragma unroll
    for (int e = 0; e < E; e++) { p[e] = __expf(lg[e] - mx); s += p[e]; }
    float inv = 1.0f / s;
    #pragma unroll
    for (int e = 0; e < E; e++) p[e] *= inv;

    // top-2, strict '>' ascending scan matches jax top_k tie-breaking
    int e0 = 0;
    #pragma unroll
    for (int e = 1; e < E; e++) if (p[e] > p[e0]) e0 = e;
    int e1 = (e0 == 0) ? 1 : 0;
    #pragma unroll
    for (int e = 0; e < E; e++) if (e != e0 && p[e] > p[e1]) e1 = e;

    float w0 = p[e0], w1 = p[e1];
    float ws = 1.0f / (w0 + w1);
    w0 *= ws; w1 *= ws;

    d_tkidx[t * 2 + 0] = e0;  d_tkidx[t * 2 + 1] = e1;
    d_tkw  [t * 2 + 0] = w0;  d_tkw  [t * 2 + 1] = w1;
    atomicAdd(&d_cnt[e0], 1);
    atomicAdd(&d_cnt[e1], 1);
}

__global__ void prefix_kernel() {
    int acc = 0;
    for (int e = 0; e < E; e++) {
        int pc = (d_cnt[e] + (BM - 1)) & ~(BM - 1);
        d_poff[e] = acc;
        d_pcnt[e] = pc;
        acc += pc;
    }
}

__global__ void assign_kernel() {
    int t = blockIdx.x * 256 + threadIdx.x;
    #pragma unroll
    for (int k = 0; k < 2; k++) {
        int e = d_tkidx[t * 2 + k];
        int s = atomicAdd(&d_cnt2[e], 1);
        int g = d_poff[e] + s;
        d_toklist[g]        = t;
        d_wrow[g]           = d_tkw[t * 2 + k];
        d_slotmap[t * 2 + k] = g;
    }
}

// ------------------------- generic tile GEMM --------------------------------
// C[rows of expert e] = A @ (B + e*sBe)   128x128x8 tiles, 256 thr, 8x8/thread
// GATHER: A row index via d_toklist (rows of global input x)
// EPI: 0 = store; 1 = C = silu(C_prev) * acc (in-place act-fuse); 2 = C = wrow * acc
template<bool GATHER, int EPI>
__device__ __forceinline__ void gemm_body(
    const float* __restrict__ A, const float* __restrict__ B,
    float* __restrict__ C, int K, int N, long sBe,
    const float* __restrict__ wr)
{
    const int e       = blockIdx.z;
    const int m0      = d_poff[e];
    const int M       = d_pcnt[e];
    const int rowTile = blockIdx.y * BM;
    if (rowTile >= M) return;

    __shared__ float As[8][BM];
    __shared__ float Bs[8][128];

    const int tid  = threadIdx.x;
    const int aRow = tid >> 1;
    const int aCol = (tid & 1) * 4;
    const int bRow = tid >> 5;
    const int bCol = (tid & 31) * 4;

    long arow;
    if (GATHER) arow = d_toklist[m0 + rowTile + aRow];
    else        arow = (long)(m0 + rowTile + aRow);
    const float* Ap = A + arow * K + aCol;
    const float* Bp = B + (long)e * sBe + (long)blockIdx.x * 128
                        + (long)bRow * N + bCol;

    const int tx = tid & 15;
    const int ty = tid >> 4;

    float acc[8][8];
    #pragma unroll
    for (int i = 0; i < 8; i++)
        #pragma unroll
        for (int j = 0; j < 8; j++) acc[i][j] = 0.0f;

    for (int kt = 0; kt < K; kt += 8) {
        float4 av = *(const float4*)(Ap + kt);
        As[aCol + 0][aRow] = av.x;
        As[aCol + 1][aRow] = av.y;
        As[aCol + 2][aRow] = av.z;
        As[aCol + 3][aRow] = av.w;
        *(float4*)(&Bs[bRow][bCol]) = *(const float4*)(Bp + (long)kt * N);
        __syncthreads();

        #pragma unroll
        for (int kk = 0; kk < 8; kk++) {
            float4 a0 = *(const float4*)(&As[kk][ty * 8]);
            float4 a1 = *(const float4*)(&As[kk][ty * 8 + 4]);
            float4 b0 = *(const float4*)(&Bs[kk][tx * 8]);
            float4 b1 = *(const float4*)(&Bs[kk][tx * 8 + 4]);
            float ra[8] = {a0.x, a0.y, a0.z, a0.w, a1.x, a1.y, a1.z, a1.w};
            float rb[8] = {b0.x, b0.y, b0.z, b0.w, b1.x, b1.y, b1.z, b1.w};
            #pragma unroll
            for (int i = 0; i < 8; i++)
                #pragma unroll
                for (int j = 0; j < 8; j++) acc[i][j] += ra[i] * rb[j];
        }
        __syncthreads();
    }

    const int crow0 = m0 + rowTile + ty * 8;
    const int ccol0 = blockIdx.x * 128 + tx * 8;
    #pragma unroll
    for (int i = 0; i < 8; i++) {
        float* cp = C + (long)(crow0 + i) * N + ccol0;
        if (EPI == 0) {
            float4 v0 = {acc[i][0], acc[i][1], acc[i][2], acc[i][3]};
            float4 v1 = {acc[i][4], acc[i][5], acc[i][6], acc[i][7]};
            *(float4*)cp       = v0;
            *(float4*)(cp + 4) = v1;
        } else if (EPI == 1) {
            float4 g0 = *(const float4*)cp;
            float4 g1 = *(const float4*)(cp + 4);
            float4 v0 = {silu_f(g0.x) * acc[i][0], silu_f(g0.y) * acc[i][1],
                         silu_f(g0.z) * acc[i][2], silu_f(g0.w) * acc[i][3]};
            float4 v1 = {silu_f(g1.x) * acc[i][4], silu_f(g1.y) * acc[i][5],
                         silu_f(g1.z) * acc[i][6], silu_f(g1.w) * acc[i][7]};
            *(float4*)cp       = v0;
            *(float4*)(cp + 4) = v1;
        } else {
            float w = wr[crow0 + i];
            float4 v0 = {w * acc[i][0], w * acc[i][1], w * acc[i][2], w * acc[i][3]};
            float4 v1 = {w * acc[i][4], w * acc[i][5], w * acc[i][6], w * acc[i][7]};
            *(float4*)cp       = v0;
            *(float4*)(cp + 4) = v1;
        }
    }
}

// Thin wrappers binding the __device__ scratch (avoids host symbol lookups)
__global__ void __launch_bounds__(256) k_pg(const float* x, const float* Ug) {
    gemm_body<true, 0>(x, Ug, d_Pg, Hd, R, (long)Hd * R, nullptr);
}
__global__ void __launch_bounds__(256) k_pu(const float* x, const float* Uu) {
    gemm_body<true, 0>(x, Uu, d_Pu, Hd, R, (long)Hd * R, nullptr);
}
__global__ void __launch_bounds__(256) k_pg2(const float* Cg) {
    gemm_body<false, 0>(d_Pg, Cg, d_Pg2, R, R, 0, nullptr);
}
__global__ void __launch_bounds__(256) k_pu2(const float* Cu) {
    gemm_body<false, 0>(d_Pu, Cu, d_Pu2, R, R, 0, nullptr);
}
__global__ void __launch_bounds__(256) k_g(const float* Vg) {
    gemm_body<false, 0>(d_Pg2, Vg, d_Abuf, R, F, (long)R * F, nullptr);
}
__global__ void __launch_bounds__(256) k_act(const float* Vu) {
    gemm_body<false, 1>(d_Pu2, Vu, d_Abuf, R, F, (long)R * F, nullptr);
}
__global__ void __launch_bounds__(256) k_qd(const float* Ud) {
    gemm_body<false, 0>(d_Abuf, Ud, d_Qd, F, R, (long)F * R, nullptr);
}
__global__ void __launch_bounds__(256) k_qd2(const float* Cd) {
    gemm_body<false, 0>(d_Qd, Cd, d_Qd2, R, R, 0, nullptr);
}
__global__ void __launch_bounds__(256) k_y(const float* Vd) {
    gemm_body<false, 2>(d_Qd2, Vd, d_Y, R, Hd, (long)R * Hd, d_wrow);
}

// Final combine: out[t] = Y[slot0(t)] + Y[slot1(t)]  (weights folded into Y)
__global__ void __launch_bounds__(256) combine_kernel(float* __restrict__ out) {
    int i = blockIdx.x * 256 + threadIdx.x;   // over T*Hd/4 float4s
    int t = i >> 8;                           // Hd/4 = 256
    int c = i & 255;
    int s0 = d_slotmap[t * 2 + 0];
    int s1 = d_slotmap[t * 2 + 1];
    const float4* Y4 = (const float4*)d_Y;
    float4 a = Y4[(long)s0 * 256 + c];
    float4 b = Y4[(long)s1 * 256 + c];
    float4 o = {a.x + b.x, a.y + b.y, a.z + b.z, a.w + b.w};
    ((float4*)out)[i] = o;
}

// ------------------------- launch -------------------------------------------
extern "C" void kernel_launch(void* const* d_in, const int* in_sizes, int n_in,
                              void* d_out, int out_size) {
    const float* x  = (const float*)d_in[0];
    const float* gw = (const float*)d_in[1];
    const float* Ug = (const float*)d_in[2];
    const float* Cg = (const float*)d_in[3];
    const float* Vg = (const float*)d_in[4];
    const float* Uu = (const float*)d_in[5];
    const float* Cu = (const float*)d_in[6];
    const float* Vu = (const float*)d_in[7];
    const float* Ud = (const float*)d_in[8];
    const float* Cd = (const float*)d_in[9];
    const float* Vd = (const float*)d_in[10];
    float* out = (float*)d_out;

    init_kernel  <<<1, 256>>>();
    gate_kernel  <<<T / 256, 256>>>(x, gw);
    prefix_kernel<<<1, 1>>>();
    assign_kernel<<<T / 256, 256>>>();

    const dim3 blk(256, 1, 1);
    k_pg  <<<dim3(R  / 128, 16, E), blk>>>(x, Ug);
    k_pu  <<<dim3(R  / 128, 16, E), blk>>>(x, Uu);
    k_pg2 <<<dim3(R  / 128, 16, E), blk>>>(Cg);
    k_pu2 <<<dim3(R  / 128, 16, E), blk>>>(Cu);
    k_g   <<<dim3(F  / 128, 16, E), blk>>>(Vg);
    k_act <<<dim3(F  / 128, 16, E), blk>>>(Vu);
    k_qd  <<<dim3(R  / 128, 16, E), blk>>>(Ud);
    k_qd2 <<<dim3(R  / 128, 16, E), blk>>>(Cd);
    k_y   <<<dim3(Hd / 128, 16, E), blk>>>(Vd);

    combine_kernel<<<(T * Hd / 4) / 256, 256>>>(out);
}